// round 17
// baseline (speedup 1.0000x reference)
#include <cuda_runtime.h>
#include <cuda_bf16.h>
#include <math.h>

// Problem constants (shapes fixed by the reference)
#define MAX_N 50000
#define MAX_E 800000
#define MAX_G 16
#define NODE_DIM 128
#define HID 64
#define HEADS 3
#define FDIM 192            // HEADS*HID
#define NEG_SLOPE 0.2f
#define SCAN_B 1024
#define MAX_BLKS 64         // ceil(50000/1024)=49

// ------------- device scratch (static; zero-init from BSS at load) --------
// Self-cleaning invariants (hold at entry of every kernel_launch call):
//   g_deg == 0          (reset by k_scan_lookback after consuming)
//   g_sumflag == 0      (reset by k_scatter)
//   g_pool == 0         (reset by k_final)
// Feat layout (pad-free): per node, lane l owns dims (2l,2l+1) of each head.
//   g_featP[node*32+l] = uint2 {head0 bf16x2, head1 bf16x2}   (12.8 MB)
//   g_featQ[node*32+l] = uint  {head2 bf16x2}                 ( 6.4 MB)
__device__ uint2  g_featP[(size_t)MAX_N * 32];
__device__ unsigned int g_featQ[(size_t)MAX_N * 32];
__device__ __nv_bfloat162 g_wb2[FDIM * 64];              // fc_w in bf16 [192][128]
__device__ float4 g_el4[MAX_N];                          // x,y,z used
__device__ float4 g_er4[MAX_N];
__device__ int    g_deg[MAX_N];
__device__ int    g_sumflag[MAX_BLKS];                   // tile_sum+1, 0=not ready
__device__ int    g_rowoff[MAX_N + 1];
__device__ int    g_cursor[MAX_N];
__device__ int    g_csrsrc[MAX_E];
__device__ float  g_pool[MAX_G * HID];

// ---------------- helpers ----------------
__device__ __forceinline__ float leaky(float x) {
    return x > 0.f ? x : NEG_SLOPE * x;
}
__device__ __forceinline__ void ldsm4(unsigned* r, unsigned addr) {
    asm volatile("ldmatrix.sync.aligned.m8n8.x4.shared.b16 {%0,%1,%2,%3}, [%4];"
                 : "=r"(r[0]), "=r"(r[1]), "=r"(r[2]), "=r"(r[3]) : "r"(addr));
}
__device__ __forceinline__ void mma16816(float* d, const unsigned* a,
                                         const unsigned* b) {
    asm volatile(
        "mma.sync.aligned.m16n8k16.row.col.f32.bf16.bf16.f32 "
        "{%0,%1,%2,%3}, {%4,%5,%6,%7}, {%8,%9}, {%0,%1,%2,%3};"
        : "+f"(d[0]), "+f"(d[1]), "+f"(d[2]), "+f"(d[3])
        : "r"(a[0]), "r"(a[1]), "r"(a[2]), "r"(a[3]), "r"(b[0]), "r"(b[1]));
}

// ---------------- K0: fc_w fp32 -> bf16 (once per run; W stays L2-hot) ----
__global__ void k_wcvt(const float* __restrict__ fc_w) {
    int i = blockIdx.x * blockDim.x + threadIdx.x;
    if (i < FDIM * 64) {
        float2 f = ((const float2*)fc_w)[i];
        g_wb2[i] = __floats2bfloat162_rn(f.x, f.y);
    }
}

// ---- K1: bf16 HMMA GEMM (mma.sync m16n8k16), fused el/er + feat stores,
//      PLUS embedded degree histogram. 512 thr, 64 nodes x 192 cols. ----
// smem: a_s [64][136] bf16 (17408B), b_s [192][136] bf16 (52224B),
//       s_e/s_r [4 nw][64][3] floats (6144B). Stride 136 bf16 = 272B:
//       ldmatrix 8-row phases hit banks {0,4,...,28} — conflict-free.
#define GM_BM 64
#define A_BYTES (64 * 136 * 2)
#define B_BYTES (192 * 136 * 2)
#define SE_OFF  (A_BYTES + B_BYTES)
#define GM_SMEM (SE_OFF + 4 * 64 * 3 * 4 * 2)

__global__ void __launch_bounds__(512) k_gemm(
    const float* __restrict__ h, const float* __restrict__ attn_l,
    const float* __restrict__ attn_r, const int* __restrict__ dst,
    int E, int N)
{
    extern __shared__ char dsm[];
    __nv_bfloat16* a_s = (__nv_bfloat16*)dsm;
    float* s_e = (float*)(dsm + SE_OFF);          // [4][64][3]
    float* s_r = s_e + 4 * 64 * 3;

    const int tid = threadIdx.x;
    const int lane = tid & 31;
    const int warp = tid >> 5;
    const int mw = warp & 3;           // rows 16*mw .. +15
    const int nw = warp >> 2;          // cols 48*nw .. +47
    const int g   = lane >> 2;
    const int tig = lane & 3;
    const int base = blockIdx.x * GM_BM;

    const unsigned sa = (unsigned)__cvta_generic_to_shared(dsm);
    const unsigned sb = sa + A_BYTES;

    // ---- stage A: h fp32 -> bf16 smem [64][136] ----
    const float4* h4 = (const float4*)h;          // [N][32]
    #pragma unroll
    for (int i = 0; i < 4; i++) {
        int F = i * 512 + tid;
        int nd = F >> 5, kq = F & 31;             // node 0..63, float4 idx
        int gn = base + nd;
        float4 v = (gn < N) ? h4[(size_t)gn * 32 + kq]
                            : make_float4(0.f, 0.f, 0.f, 0.f);
        __nv_bfloat162 b0 = __floats2bfloat162_rn(v.x, v.y);
        __nv_bfloat162 b1 = __floats2bfloat162_rn(v.z, v.w);
        *(__nv_bfloat162*)((char*)a_s + nd * 272 + kq * 8)     = b0;
        *(__nv_bfloat162*)((char*)a_s + nd * 272 + kq * 8 + 4) = b1;
    }
    // ---- stage B: g_wb2 (packed bf16) -> smem [192][136] ----
    // Each W row = 128 bf16 = 256 B = 16 uint4. 192 rows * 16 = 3072 = 6*512.
    const uint4* wb4 = (const uint4*)g_wb2;       // [192][16 uint4]
    #pragma unroll
    for (int i = 0; i < 6; i++) {
        int F = i * 512 + tid;
        int c = F >> 4, q = F & 15;               // row, uint4-in-row
        uint4 u = wb4[c * 16 + q];
        *(uint4*)(dsm + A_BYTES + c * 272 + q * 16) = u;
    }
    __syncthreads();

    // ---- ldmatrix source addresses ----
    const int row_a = 16 * mw + (lane & 7) + ((lane >> 3) & 1) * 8;
    const unsigned a_addr0 = sa + row_a * 272 + (lane >> 4) * 16;
    unsigned b_addr0[3];
    #pragma unroll
    for (int j = 0; j < 3; j++) {
        int row_b = 48 * nw + 16 * j + (lane & 7) + ((lane >> 4) & 1) * 8;
        b_addr0[j] = sb + row_b * 272 + ((lane >> 3) & 1) * 16;
    }

    float acc[6][4];
    #pragma unroll
    for (int j = 0; j < 6; j++)
        #pragma unroll
        for (int q = 0; q < 4; q++) acc[j][q] = 0.f;

    #pragma unroll
    for (int ks = 0; ks < 8; ks++) {
        unsigned a[4];
        ldsm4(a, a_addr0 + ks * 32);
        unsigned b[3][4];
        #pragma unroll
        for (int j = 0; j < 3; j++) ldsm4(b[j], b_addr0[j] + ks * 32);
        #pragma unroll
        for (int j = 0; j < 3; j++) {
            mma16816(acc[2 * j],     a, &b[j][0]);
            mma16816(acc[2 * j + 1], a, &b[j][2]);
        }
    }

    // ---- epilogue: feat bf16 stores + el/er ----
    const int node0 = base + 16 * mw + g;     // rows: node0, node0+8
    const int node1 = node0 + 8;
    float e0a[3] = {0.f, 0.f, 0.f}, r0a[3] = {0.f, 0.f, 0.f};
    float e1a[3] = {0.f, 0.f, 0.f}, r1a[3] = {0.f, 0.f, 0.f};

    char* pp0 = (char*)g_featP + (size_t)node0 * 256;
    char* qq0 = (char*)g_featQ + (size_t)node0 * 128;
    char* pp1 = (char*)g_featP + (size_t)node1 * 256;
    char* qq1 = (char*)g_featQ + (size_t)node1 * 128;

    #pragma unroll
    for (int j = 0; j < 6; j++) {
        const int c = 48 * nw + 8 * j + 2 * tig;   // even; c,c+1 same head
        const int hd = c >> 6;
        const int p = (c & 63) >> 1;
        float al0 = __ldg(&attn_l[c]), al1 = __ldg(&attn_l[c + 1]);
        float ar0 = __ldg(&attn_r[c]), ar1 = __ldg(&attn_r[c + 1]);
        e0a[hd] += acc[j][0] * al0 + acc[j][1] * al1;
        r0a[hd] += acc[j][0] * ar0 + acc[j][1] * ar1;
        e1a[hd] += acc[j][2] * al0 + acc[j][3] * al1;
        r1a[hd] += acc[j][2] * ar0 + acc[j][3] * ar1;
        __nv_bfloat162 u0 = __floats2bfloat162_rn(acc[j][0], acc[j][1]);
        __nv_bfloat162 u1 = __floats2bfloat162_rn(acc[j][2], acc[j][3]);
        if (node0 < N) {
            if (hd < 2) *(__nv_bfloat162*)(pp0 + p * 8 + hd * 4) = u0;
            else        *(__nv_bfloat162*)(qq0 + p * 4) = u0;
        }
        if (node1 < N) {
            if (hd < 2) *(__nv_bfloat162*)(pp1 + p * 8 + hd * 4) = u1;
            else        *(__nv_bfloat162*)(qq1 + p * 4) = u1;
        }
    }

    // quad-reduce (lanes 4g..4g+3 share a row)
    #pragma unroll
    for (int o = 1; o <= 2; o <<= 1) {
        #pragma unroll
        for (int hd = 0; hd < 3; hd++) {
            e0a[hd] += __shfl_xor_sync(0xffffffffu, e0a[hd], o);
            r0a[hd] += __shfl_xor_sync(0xffffffffu, r0a[hd], o);
            e1a[hd] += __shfl_xor_sync(0xffffffffu, e1a[hd], o);
            r1a[hd] += __shfl_xor_sync(0xffffffffu, r1a[hd], o);
        }
    }
    if (tig == 0) {
        int nl0 = 16 * mw + g, nl1 = nl0 + 8;
        #pragma unroll
        for (int hd = 0; hd < 3; hd++) {
            s_e[(nw * 64 + nl0) * 3 + hd] = e0a[hd];
            s_r[(nw * 64 + nl0) * 3 + hd] = r0a[hd];
            s_e[(nw * 64 + nl1) * 3 + hd] = e1a[hd];
            s_r[(nw * 64 + nl1) * 3 + hd] = r1a[hd];
        }
    }
    __syncthreads();
    if (tid < GM_BM) {
        int node = base + tid;
        if (node < N) {
            float el[3], er[3];
            #pragma unroll
            for (int hd = 0; hd < 3; hd++) {
                el[hd] = s_e[(0 * 64 + tid) * 3 + hd] + s_e[(1 * 64 + tid) * 3 + hd]
                       + s_e[(2 * 64 + tid) * 3 + hd] + s_e[(3 * 64 + tid) * 3 + hd];
                er[hd] = s_r[(0 * 64 + tid) * 3 + hd] + s_r[(1 * 64 + tid) * 3 + hd]
                       + s_r[(2 * 64 + tid) * 3 + hd] + s_r[(3 * 64 + tid) * 3 + hd];
            }
            g_el4[node] = make_float4(el[0], el[1], el[2], 0.f);
            g_er4[node] = make_float4(er[0], er[1], er[2], 0.f);
        }
    }

    // ---- embedded degree histogram: this block's slice of edges ----
    {
        int eb = (E + gridDim.x - 1) / gridDim.x;
        int e0 = blockIdx.x * eb;
        int e1 = e0 + eb; if (e1 > E) e1 = E;
        for (int i = e0 + tid; i < e1; i += 512)
            atomicAdd(&g_deg[dst[i]], 1);
    }
}

// ------- CSR scan: single kernel, decoupled lookback (49 blocks, all
//         resident -> spin-safe). Also resets g_deg. --------------------
__global__ void __launch_bounds__(SCAN_B) k_scan_lookback(int N) {
    __shared__ int wsum[32];
    __shared__ int s_total;
    __shared__ int s_off;
    const int t = threadIdx.x, lane = t & 31, w = t >> 5;
    if (t == 0) s_off = 0;

    int idx = blockIdx.x * SCAN_B + t;
    int v = (idx < N) ? g_deg[idx] : 0;
    int x = v;
    #pragma unroll
    for (int o = 1; o < 32; o <<= 1) {
        int y = __shfl_up_sync(0xffffffffu, x, o);
        if (lane >= o) x += y;
    }
    if (lane == 31) wsum[w] = x;
    __syncthreads();
    if (w == 0) {
        int s = wsum[lane], sc = s;
        #pragma unroll
        for (int o = 1; o < 32; o <<= 1) {
            int y = __shfl_up_sync(0xffffffffu, sc, o);
            if (lane >= o) sc += y;
        }
        if (lane == 31) s_total = sc;
        wsum[lane] = sc - s;
    }
    __syncthreads();
    const int excl = (x - v) + wsum[w];

    if (t == 0) {
        int S = s_total;
        __threadfence();
        *(volatile int*)&g_sumflag[blockIdx.x] = S + 1;
    }
    if (t < blockIdx.x) {
        volatile int* sf = g_sumflag;
        int tv;
        do { tv = sf[t]; } while (tv == 0);
        atomicAdd(&s_off, tv - 1);
    }
    __syncthreads();
    const int off = s_off;

    if (idx < N) {
        int ro = excl + off;
        g_rowoff[idx] = ro;
        g_cursor[idx] = ro;
        g_deg[idx] = 0;                      // self-clean
        if (idx == N - 1) g_rowoff[N] = ro + v;
    }
}

// ---------------- CSR scatter (+ sumflag reset) ----------------
__global__ void k_scatter(const int* __restrict__ src, const int* __restrict__ dst, int E) {
    if (blockIdx.x == 0 && threadIdx.x < MAX_BLKS)
        g_sumflag[threadIdx.x] = 0;          // self-clean for next run
    int i = blockIdx.x * blockDim.x + threadIdx.x;
    if (i < E) {
        int d = dst[i];
        int pos = atomicAdd(&g_cursor[d], 1);
        g_csrsrc[pos] = src[i];
    }
}

// ---------------- K3: fused GAT softmax + aggregation + pool --------------
__global__ void __launch_bounds__(256) k_gat(
    const int* __restrict__ graph_id, const float* __restrict__ bias, int N)
{
    __shared__ float s_pool[64];
    __shared__ int s_gid;
    const int tid = threadIdx.x;
    const int lane = tid & 31;
    const int node = (blockIdx.x << 3) + (tid >> 5);

    if (tid < 64) s_pool[tid] = 0.f;
    if (tid == 0) {
        int n0 = blockIdx.x << 3;
        s_gid = graph_id[n0 < N ? n0 : (N - 1)];
    }
    __syncthreads();

    const bool vn = node < N;
    const int begin = vn ? g_rowoff[node] : 0;
    const int end   = vn ? g_rowoff[node + 1] : 0;
    const float4 er = vn ? g_er4[node] : make_float4(0.f, 0.f, 0.f, 0.f);

    float s0 = 0.f, s1 = 0.f, s2 = 0.f;
    float a0 = 0.f, a1 = 0.f, a2 = 0.f, a3 = 0.f, a4 = 0.f, a5 = 0.f;

    for (int b = begin; b < end; b += 32) {
        const int i = b + lane;
        const bool act = i < end;
        int mys = act ? g_csrsrc[i] : 0;
        float4 el = g_el4[mys];
        float ex0 = __expf(leaky(el.x + er.x));
        float ex1 = __expf(leaky(el.y + er.y));
        float ex2 = __expf(leaky(el.z + er.z));
        if (act) { s0 += ex0; s1 += ex1; s2 += ex2; }

        int cnt = end - b; if (cnt > 32) cnt = 32;
        #pragma unroll 8
        for (int j = 0; j < cnt; j++) {
            int   s  = __shfl_sync(0xffffffffu, mys, j);
            float e0 = __shfl_sync(0xffffffffu, ex0, j);
            float e1 = __shfl_sync(0xffffffffu, ex1, j);
            float e2 = __shfl_sync(0xffffffffu, ex2, j);
            uint2 u01 = __ldg(&g_featP[(size_t)s * 32 + lane]);
            unsigned int u2 = __ldg(&g_featQ[(size_t)s * 32 + lane]);
            float2 f0 = __bfloat1622float2(*(__nv_bfloat162*)&u01.x);
            float2 f1 = __bfloat1622float2(*(__nv_bfloat162*)&u01.y);
            float2 f2 = __bfloat1622float2(*(__nv_bfloat162*)&u2);
            a0 += e0 * f0.x;  a1 += e0 * f0.y;
            a2 += e1 * f1.x;  a3 += e1 * f1.y;
            a4 += e2 * f2.x;  a5 += e2 * f2.y;
        }
    }

    #pragma unroll
    for (int o = 16; o > 0; o >>= 1) {
        s0 += __shfl_xor_sync(0xffffffffu, s0, o);
        s1 += __shfl_xor_sync(0xffffffffu, s1, o);
        s2 += __shfl_xor_sync(0xffffffffu, s2, o);
    }

    const bool has = end > begin;
    const float i0 = has ? 1.f / s0 : 0.f;
    const float i1 = has ? 1.f / s1 : 0.f;
    const float i2 = has ? 1.f / s2 : 0.f;

    const int d0 = 2 * lane, d1 = 2 * lane + 1;
    const float third = 1.f / 3.f;
    float hd0 = (a0 * i0 + a2 * i1 + a4 * i2
                 + bias[d0] + bias[64 + d0] + bias[128 + d0]) * third;
    float hd1 = (a1 * i0 + a3 * i1 + a5 * i2
                 + bias[d1] + bias[64 + d1] + bias[128 + d1]) * third;

    if (vn) {
        int g = graph_id[node];
        if (g == s_gid) {
            atomicAdd(&s_pool[d0], hd0);
            atomicAdd(&s_pool[d1], hd1);
        } else {
            atomicAdd(&g_pool[g * HID + d0], hd0);
            atomicAdd(&g_pool[g * HID + d1], hd1);
        }
    }
    __syncthreads();
    if (tid < 64) atomicAdd(&g_pool[s_gid * HID + tid], s_pool[tid]);
}

// ---------------- K4: final MLP + sigmoid (+ pool reset) ----------------
__device__ __forceinline__ int lbound(const int* __restrict__ a, int n, int key) {
    int lo = 0, hi = n;
    while (lo < hi) {
        int mid = (lo + hi) >> 1;
        if (a[mid] < key) lo = mid + 1; else hi = mid;
    }
    return lo;
}

__global__ void k_final(
    const float* __restrict__ z, const float* __restrict__ lin1_w,
    const float* __restrict__ lin1_b, const float* __restrict__ lin2_w,
    const float* __restrict__ lin2_b, const int* __restrict__ graph_id,
    float* __restrict__ out, int G, int N)
{
    const int w = threadIdx.x >> 5;
    const int lane = threadIdx.x & 31;
    if (w >= G) return;

    float z1a = lin1_b[lane], z1b = lin1_b[lane + 32];
    const float* zr = &z[w * 128];
    const float* w1a = &lin1_w[lane * 128];
    const float* w1b = &lin1_w[(lane + 32) * 128];
    #pragma unroll 4
    for (int k = 0; k < 128; k++) {
        float zv = zr[k];
        z1a += zv * w1a[k];
        z1b += zv * w1b[k];
    }

    int cnt = 0;
    if (lane == 0)
        cnt = lbound(graph_id, N, w + 1) - lbound(graph_id, N, w);
    cnt = __shfl_sync(0xffffffffu, cnt, 0);

    float invc = 1.f / fmaxf((float)cnt, 1.f);
    float pa = g_pool[w * HID + lane] * invc;
    float pb = g_pool[w * HID + 32 + lane] * invc;

    g_pool[w * HID + lane] = 0.f;
    g_pool[w * HID + 32 + lane] = 0.f;

    float part = lin2_w[lane] * pa + lin2_w[32 + lane] * pb
               + lin2_w[64 + lane] * z1a + lin2_w[96 + lane] * z1b;
    #pragma unroll
    for (int o = 16; o > 0; o >>= 1)
        part += __shfl_down_sync(0xffffffffu, part, o);

    if (lane == 0) {
        float v = part + lin2_b[0];
        out[w] = 1.f / (1.f + expf(-v));
    }
}

// ---------------- launch ----------------
extern "C" void kernel_launch(void* const* d_in, const int* in_sizes, int n_in,
                              void* d_out, int out_size)
{
    const float* h        = (const float*)d_in[0];
    const float* z        = (const float*)d_in[1];
    const int*   src      = (const int*)  d_in[2];
    const int*   dst      = (const int*)  d_in[3];
    const int*   graph_id = (const int*)  d_in[4];
    const float* fc_w     = (const float*)d_in[5];
    const float* attn_l   = (const float*)d_in[6];
    const float* attn_r   = (const float*)d_in[7];
    const float* bias     = (const float*)d_in[8];
    const float* lin1_w   = (const float*)d_in[9];
    const float* lin1_b   = (const float*)d_in[10];
    const float* lin2_w   = (const float*)d_in[11];
    const float* lin2_b   = (const float*)d_in[12];

    const int N = in_sizes[0] / NODE_DIM;   // 50000
    const int E = in_sizes[2];              // 800000
    const int G = in_sizes[1] / 128;        // 16
    const int NB = (N + SCAN_B - 1) / SCAN_B;  // 49

    cudaFuncSetAttribute(k_gemm, cudaFuncAttributeMaxDynamicSharedMemorySize,
                         GM_SMEM);

    k_wcvt<<<(FDIM * 64 + 255) / 256, 256>>>(fc_w);                    // 1
    k_gemm<<<(N + GM_BM - 1) / GM_BM, 512, GM_SMEM>>>(h, attn_l,       // 2
                                                      attn_r, dst, E, N);
    k_scan_lookback<<<NB, SCAN_B>>>(N);                                // 3
    k_scatter<<<(E + 255) / 256, 256>>>(src, dst, E);                  // 4
    k_gat<<<(N + 7) / 8, 256>>>(graph_id, bias, N);                    // 5
    k_final<<<1, 32 * G>>>(z, lin1_w, lin1_b, lin2_w, lin2_b,          // 6
                           graph_id, (float*)d_out, G, N);
}